// round 14
// baseline (speedup 1.0000x reference)
#include <cuda_runtime.h>
#include <cstdint>

#define LW 49
#define DK 32
#define NH 8
#define NW 64
#define LP 52      // padded k row length (13 float4)
#define RST 50     // bias+mask row stride (8B-aligned pairs)
#define BMSZ 2452  // 49*50 padded to float4 multiple

// Fused (bias + mask) for each of the 512 (h,w) combos, rows padded to RST.
__device__ float g_bm[NH * NW * BMSZ];

__global__ void bm_prep_kernel(const float* __restrict__ table,
                               const int* __restrict__ idx,
                               const float* __restrict__ mask) {
    const int hw = blockIdx.x;          // h*NW + w
    const int h  = hw >> 6;
    const int w  = hw & (NW - 1);
    float* __restrict__ dst = g_bm + (size_t)hw * BMSZ;
    const float* __restrict__ mg = mask + (size_t)w * (LW * LW);
    for (int i = threadIdx.x; i < BMSZ; i += blockDim.x) {
        int t = i / RST, s = i - t * RST;
        float v = 0.f;
        if (t < LW && s < LW) v = table[idx[t * LW + s] * NH + h] + mg[t * LW + s];
        dst[i] = v;
    }
}

// ---- packed fp32 helpers (Blackwell f32x2 path) ----
__device__ __forceinline__ unsigned long long fma2(unsigned long long a,
                                                   unsigned long long b,
                                                   unsigned long long c) {
    unsigned long long d;
    asm("fma.rn.f32x2 %0, %1, %2, %3;" : "=l"(d) : "l"(a), "l"(b), "l"(c));
    return d;
}
__device__ __forceinline__ unsigned long long mul2(unsigned long long a,
                                                   unsigned long long b) {
    unsigned long long d;
    asm("mul.rn.f32x2 %0, %1, %2;" : "=l"(d) : "l"(a), "l"(b));
    return d;
}
__device__ __forceinline__ unsigned long long pack2(float x, float y) {
    unsigned long long d;
    asm("mov.b64 %0, {%1, %2};" : "=l"(d) : "f"(x), "f"(y));
    return d;
}
__device__ __forceinline__ void unpack2(unsigned long long p, float& x, float& y) {
    asm("mov.b64 {%0, %1}, %2;" : "=f"(x), "=f"(y) : "l"(p));
}
__device__ __forceinline__ void lds_v2u64(uint32_t a, unsigned long long& x,
                                          unsigned long long& y) {
    asm volatile("ld.shared.v2.u64 {%0, %1}, [%2];" : "=l"(x), "=l"(y) : "r"(a));
}
__device__ __forceinline__ unsigned long long lds_u64(uint32_t a) {
    unsigned long long v;
    asm volatile("ld.shared.u64 %0, [%1];" : "=l"(v) : "r"(a));
    return v;
}
__device__ __forceinline__ void sts_u64(uint32_t a, unsigned long long v) {
    asm volatile("st.shared.u64 [%0], %1;" :: "r"(a), "l"(v));
}
__device__ __forceinline__ float lds_f32(uint32_t a) {
    float v;
    asm volatile("ld.shared.f32 %0, [%1];" : "=f"(v) : "r"(a));
    return v;
}

// CTA = 4 warps = 4 (b,h) pairs sharing one (h,w) bias+mask tile.
// Warp lane i computes attention rows i and i+32.
__global__ __launch_bounds__(128, 4)   // cap at 128 regs -> 16 warps/SM
void win_attn_kernel(const float* __restrict__ q,
                     const float* __restrict__ k,
                     float* __restrict__ out_score,
                     float* __restrict__ out_attn) {
    __shared__ __align__(16) float ks[4][DK * LP];
    __shared__ __align__(16) float bm[BMSZ];

    const int tid  = threadIdx.x;
    const int wid  = tid >> 5;
    const int lane = tid & 31;

    const int cta = blockIdx.x;           // 64*8*8 = 4096 CTAs
    const int w   = cta & 63;
    const int h   = (cta >> 6) & 7;
    const int grp = cta >> 9;             // 0..7
    const int b   = w + 64 * (grp * 4 + wid);
    const int bh  = b * 8 + h;

    const float* __restrict__ qg = q + (size_t)bh * (DK * LW);
    const float* __restrict__ kg = k + (size_t)bh * (DK * LW);

    // ---- stage k (per warp) and shared bias+mask (whole CTA) ----
    for (int i = lane; i < 96; i += 32) {
        int c = i / 3, r = i - c * 3;
        ks[wid][c * LP + 49 + r] = 0.f;
    }
    for (int j = lane; j < 392; j += 32) {
        float4 kv = ((const float4*)kg)[j];
        float ka[4] = {kv.x, kv.y, kv.z, kv.w};
        int e = j * 4;
        int c = e / LW;                 // single divide per float4
        int t = e - c * LW;
        #pragma unroll
        for (int u = 0; u < 4; u++) {
            ks[wid][c * LP + t] = ka[u];
            if (++t == LW) { t = 0; ++c; }
        }
    }
    {
        const float* __restrict__ bmg = g_bm + (size_t)(h * NW + w) * BMSZ;
        for (int i = tid; i < BMSZ / 4; i += 128)
            ((float4*)bm)[i] = ((const float4*)bmg)[i];
    }
    __syncthreads();

    const uint32_t ksb = (uint32_t)__cvta_generic_to_shared(&ks[wid][0]);
    const uint32_t bmb = (uint32_t)__cvta_generic_to_shared(&bm[0]);

    const int  r0 = lane;
    const bool v1 = (lane < 17);
    const int  r1 = v1 ? lane + 32 : 48;   // clamped; results discarded when !v1

    // ---- phase 1: packed logits, 2 rows/thread; q streamed from gmem ----
    unsigned long long acc0[26], acc1[26];
    #pragma unroll
    for (int p = 0; p < 26; p++) { acc0[p] = 0ull; acc1[p] = 0ull; }

    #pragma unroll 4
    for (int c = 0; c < DK; c++) {
        const uint32_t rowb = ksb + (uint32_t)(c * LP) * 4u;
        float q0 = __ldg(qg + c * LW + r0);      // coalesced across lanes
        float q1 = __ldg(qg + c * LW + r1);      // coalesced across lanes
        unsigned long long q0p = pack2(q0, q0);
        unsigned long long q1p = pack2(q1, q1);
        #pragma unroll
        for (int j = 0; j < 13; j++) {
            unsigned long long k0, k1;
            lds_v2u64(rowb + j * 16, k0, k1);
            acc0[2 * j]     = fma2(q0p, k0, acc0[2 * j]);
            acc0[2 * j + 1] = fma2(q0p, k1, acc0[2 * j + 1]);
            acc1[2 * j]     = fma2(q1p, k0, acc1[2 * j]);
            acc1[2 * j + 1] = fma2(q1p, k1, acc1[2 * j + 1]);
        }
    }

    // ---- softmax (packed; 4-way tree reductions for max and sum) ----
    const float scale = 0.17677669529663687f;  // 32^-0.5
    const unsigned long long scale2 = pack2(scale, scale);
    const uint32_t bmr0 = bmb + (uint32_t)(r0 * RST) * 4u;
    const uint32_t bmr1 = bmb + (uint32_t)(r1 * RST) * 4u;

    #define SOFTMAX_ROW(ACC, BMR)                                            \
    {                                                                        \
        float u, v;                                                          \
        float m0 = -1e30f, m1 = -1e30f, m2 = -1e30f, m3 = -1e30f;            \
        _Pragma("unroll")                                                    \
        for (int p = 0; p < 24; p++) {                                       \
            ACC[p] = fma2(ACC[p], scale2, lds_u64(BMR + p * 8));             \
            unpack2(ACC[p], u, v);                                           \
            float uv = fmaxf(u, v);                                          \
            if ((p & 3) == 0) m0 = fmaxf(m0, uv);                            \
            else if ((p & 3) == 1) m1 = fmaxf(m1, uv);                       \
            else if ((p & 3) == 2) m2 = fmaxf(m2, uv);                       \
            else m3 = fmaxf(m3, uv);                                         \
        }                                                                    \
        unpack2(ACC[24], u, v);                                              \
        float x48 = fmaf(u, scale, lds_f32(BMR + 48 * 4));                   \
        float mx = fmaxf(fmaxf(fmaxf(m0, m1), fmaxf(m2, m3)), x48);          \
        float s0 = 0.f, s1 = 0.f, s2 = 0.f, s3 = 0.f;                        \
        _Pragma("unroll")                                                    \
        for (int p = 0; p < 24; p++) {                                       \
            unpack2(ACC[p], u, v);                                           \
            u = __expf(u - mx); v = __expf(v - mx);                          \
            if ((p & 3) == 0) s0 += u + v;                                   \
            else if ((p & 3) == 1) s1 += u + v;                              \
            else if ((p & 3) == 2) s2 += u + v;                              \
            else s3 += u + v;                                                \
            ACC[p] = pack2(u, v);                                            \
        }                                                                    \
        float e48 = __expf(x48 - mx);                                        \
        float sum = ((s0 + s1) + (s2 + s3)) + e48;                           \
        ACC[24] = pack2(e48, 0.f);                                           \
        float inv = 1.0f / sum;                                              \
        unsigned long long inv2 = pack2(inv, inv);                           \
        _Pragma("unroll")                                                    \
        for (int p = 0; p < 25; p++) ACC[p] = mul2(ACC[p], inv2);            \
        ACC[25] = 0ull;                                                      \
    }

    SOFTMAX_ROW(acc0, bmr0)
    SOFTMAX_ROW(acc1, bmr1)

    // ---- phase 2: score[c][t] = sum_s p[s] * k[c][s] (V := K) ----
    float* __restrict__ og = out_score + (size_t)bh * (DK * LW);
    #pragma unroll 2
    for (int c = 0; c < DK; c++) {
        const uint32_t rowb = ksb + (uint32_t)(c * LP) * 4u;
        unsigned long long s0 = 0ull, s1 = 0ull;
        #pragma unroll
        for (int j = 0; j < 13; j++) {
            unsigned long long k0, k1;
            lds_v2u64(rowb + j * 16, k0, k1);
            s0 = fma2(acc0[2 * j], k0, s0);
            s0 = fma2(acc0[2 * j + 1], k1, s0);
            s1 = fma2(acc1[2 * j], k0, s1);
            s1 = fma2(acc1[2 * j + 1], k1, s1);
        }
        float a, bb, x, y;
        unpack2(s0, a, bb);
        unpack2(s1, x, y);
        og[c * LW + r0] = a + bb;
        if (v1) og[c * LW + r1] = x + y;
    }
    __syncwarp();

    // ---- attn write-out, staging through ks[wid] (dead after phase 2) ----
    float* __restrict__ ag = out_attn + (size_t)bh * (LW * LW);

    // chunk A: rows 0..31 (each lane's r0 row), 32*50 = 1600 <= 1664 floats
    #pragma unroll
    for (int p = 0; p < 25; p++) sts_u64(ksb + (uint32_t)(lane * RST) * 4u + p * 8, acc0[p]);
    __syncwarp();
    for (int i = lane; i < 32 * LW; i += 32) {
        int t = i / LW, s = i - t * LW;
        ag[i] = ks[wid][t * RST + s];
    }
    __syncwarp();

    // chunk B: rows 32..48 (lanes 0..16 hold them), 17*50 = 850 floats
    if (v1) {
        #pragma unroll
        for (int p = 0; p < 25; p++) sts_u64(ksb + (uint32_t)(lane * RST) * 4u + p * 8, acc1[p]);
    }
    __syncwarp();
    for (int i = lane; i < 17 * LW; i += 32) {
        int t = i / LW, s = i - t * LW;
        ag[32 * LW + i] = ks[wid][t * RST + s];
    }
}

extern "C" void kernel_launch(void* const* d_in, const int* in_sizes, int n_in,
                              void* d_out, int out_size) {
    const float* q     = (const float*)d_in[0];
    const float* k     = (const float*)d_in[1];
    // d_in[2] (v) unused: reference sets v := k
    const float* mask  = (const float*)d_in[3];
    const float* table = (const float*)d_in[4];
    const int*   idx   = (const int*)d_in[5];

    float* out       = (float*)d_out;
    float* out_score = out;                            // 2048*256*49
    float* out_attn  = out + (size_t)2048 * 256 * 49;  // 2048*8*49*49

    bm_prep_kernel<<<NH * NW, 256>>>(table, idx, mask);
    win_attn_kernel<<<NW * NH * 8, 128>>>(q, k, out_score, out_attn);
}

// round 15
// speedup vs baseline: 1.0172x; 1.0172x over previous
#include <cuda_runtime.h>
#include <cstdint>

#define LW 49
#define DK 32
#define NH 8
#define NW 64
#define LP 52      // padded k row length (13 float4)
#define RST 50     // bias+mask row stride (8B-aligned pairs)
#define BMSZ 2452  // 49*50 padded to float4 multiple

// Fused (bias + mask) for each of the 512 (h,w) combos, rows padded to RST.
__device__ float g_bm[NH * NW * BMSZ];

__global__ void bm_prep_kernel(const float* __restrict__ table,
                               const int* __restrict__ idx,
                               const float* __restrict__ mask) {
    const int hw = blockIdx.x;          // h*NW + w
    const int h  = hw >> 6;
    const int w  = hw & (NW - 1);
    float* __restrict__ dst = g_bm + (size_t)hw * BMSZ;
    const float* __restrict__ mg = mask + (size_t)w * (LW * LW);
    for (int i = threadIdx.x; i < BMSZ; i += blockDim.x) {
        int t = i / RST, s = i - t * RST;
        float v = 0.f;
        if (t < LW && s < LW) v = table[idx[t * LW + s] * NH + h] + mg[t * LW + s];
        dst[i] = v;
    }
}

// ---- packed fp32 helpers (Blackwell f32x2 path) ----
__device__ __forceinline__ unsigned long long fma2(unsigned long long a,
                                                   unsigned long long b,
                                                   unsigned long long c) {
    unsigned long long d;
    asm("fma.rn.f32x2 %0, %1, %2, %3;" : "=l"(d) : "l"(a), "l"(b), "l"(c));
    return d;
}
__device__ __forceinline__ unsigned long long mul2(unsigned long long a,
                                                   unsigned long long b) {
    unsigned long long d;
    asm("mul.rn.f32x2 %0, %1, %2;" : "=l"(d) : "l"(a), "l"(b));
    return d;
}
__device__ __forceinline__ unsigned long long pack2(float x, float y) {
    unsigned long long d;
    asm("mov.b64 %0, {%1, %2};" : "=l"(d) : "f"(x), "f"(y));
    return d;
}
__device__ __forceinline__ void unpack2(unsigned long long p, float& x, float& y) {
    asm("mov.b64 {%0, %1}, %2;" : "=f"(x), "=f"(y) : "l"(p));
}
__device__ __forceinline__ void lds_v2u64(uint32_t a, unsigned long long& x,
                                          unsigned long long& y) {
    asm volatile("ld.shared.v2.u64 {%0, %1}, [%2];" : "=l"(x), "=l"(y) : "r"(a));
}
__device__ __forceinline__ unsigned long long lds_u64(uint32_t a) {
    unsigned long long v;
    asm volatile("ld.shared.u64 %0, [%1];" : "=l"(v) : "r"(a));
    return v;
}
__device__ __forceinline__ void sts_u64(uint32_t a, unsigned long long v) {
    asm volatile("st.shared.u64 [%0], %1;" :: "r"(a), "l"(v));
}
__device__ __forceinline__ float lds_f32(uint32_t a) {
    float v;
    asm volatile("ld.shared.f32 %0, [%1];" : "=f"(v) : "r"(a));
    return v;
}

// CTA = 128 threads = 2 (b,h) pairs sharing one (h,w) bias+mask tile.
// Warps (0,1) -> pair 0, warps (2,3) -> pair 1.
// Each thread computes ONE attention row: row = (wid&1)*32 + lane.
__global__ __launch_bounds__(128, 4)
void win_attn_kernel(const float* __restrict__ q,
                     const float* __restrict__ k,
                     float* __restrict__ out_score,
                     float* __restrict__ out_attn) {
    __shared__ __align__(16) float ks[2][DK * LP];
    __shared__ __align__(16) float bm[BMSZ];

    const int tid   = threadIdx.x;
    const int wid   = tid >> 5;
    const int lane  = tid & 31;
    const int pairi = wid >> 1;           // 0 or 1
    const int sub   = wid & 1;            // 0: rows 0..31, 1: rows 32..48
    const int tid64 = tid & 63;           // id within the pair's 64 threads

    const int cta = blockIdx.x;           // 64*8*16 = 8192 CTAs
    const int w   = cta & 63;
    const int h   = (cta >> 6) & 7;
    const int grp = cta >> 9;             // 0..15
    const int b   = w + 64 * (grp * 2 + pairi);
    const int bh  = b * 8 + h;

    const float* __restrict__ qg = q + (size_t)bh * (DK * LW);
    const float* __restrict__ kg = k + (size_t)bh * (DK * LW);

    // ---- stage k (64 threads per pair) and shared bias+mask (whole CTA) ----
    for (int i = tid64; i < 96; i += 64) {
        int c = i / 3, r = i - c * 3;
        ks[pairi][c * LP + 49 + r] = 0.f;
    }
    for (int j = tid64; j < 392; j += 64) {
        float4 kv = ((const float4*)kg)[j];
        float ka[4] = {kv.x, kv.y, kv.z, kv.w};
        int e = j * 4;
        int c = e / LW;                 // single divide per float4
        int t = e - c * LW;
        #pragma unroll
        for (int u = 0; u < 4; u++) {
            ks[pairi][c * LP + t] = ka[u];
            if (++t == LW) { t = 0; ++c; }
        }
    }
    {
        const float* __restrict__ bmg = g_bm + (size_t)(h * NW + w) * BMSZ;
        for (int i = tid; i < BMSZ / 4; i += 128)
            ((float4*)bm)[i] = ((const float4*)bmg)[i];
    }
    __syncthreads();

    const uint32_t ksb = (uint32_t)__cvta_generic_to_shared(&ks[pairi][0]);
    const uint32_t bmb = (uint32_t)__cvta_generic_to_shared(&bm[0]);

    const bool valid = (sub == 0) || (lane < 17);
    const int  row   = valid ? (sub * 32 + lane) : 48;  // clamp; discard when !valid

    // ---- phase 1: packed logits, 1 row/thread; q streamed from gmem ----
    unsigned long long acc[26];
    #pragma unroll
    for (int p = 0; p < 26; p++) acc[p] = 0ull;

    #pragma unroll 4
    for (int c = 0; c < DK; c++) {
        const uint32_t rowb = ksb + (uint32_t)(c * LP) * 4u;
        float q0 = __ldg(qg + c * LW + row);     // coalesced across lanes
        unsigned long long qp = pack2(q0, q0);
        #pragma unroll
        for (int j = 0; j < 13; j++) {
            unsigned long long k0, k1;
            lds_v2u64(rowb + j * 16, k0, k1);
            acc[2 * j]     = fma2(qp, k0, acc[2 * j]);
            acc[2 * j + 1] = fma2(qp, k1, acc[2 * j + 1]);
        }
    }

    // ---- softmax (packed; 4-way tree reductions for max and sum) ----
    const float scale = 0.17677669529663687f;  // 32^-0.5
    const unsigned long long scale2 = pack2(scale, scale);
    const uint32_t bmr = bmb + (uint32_t)(row * RST) * 4u;
    {
        float u, v;
        float m0 = -1e30f, m1 = -1e30f, m2 = -1e30f, m3 = -1e30f;
        #pragma unroll
        for (int p = 0; p < 24; p++) {
            acc[p] = fma2(acc[p], scale2, lds_u64(bmr + p * 8));
            unpack2(acc[p], u, v);
            float uv = fmaxf(u, v);
            if ((p & 3) == 0) m0 = fmaxf(m0, uv);
            else if ((p & 3) == 1) m1 = fmaxf(m1, uv);
            else if ((p & 3) == 2) m2 = fmaxf(m2, uv);
            else m3 = fmaxf(m3, uv);
        }
        unpack2(acc[24], u, v);
        float x48 = fmaf(u, scale, lds_f32(bmr + 48 * 4));
        float mx = fmaxf(fmaxf(fmaxf(m0, m1), fmaxf(m2, m3)), x48);
        float s0 = 0.f, s1 = 0.f, s2 = 0.f, s3 = 0.f;
        #pragma unroll
        for (int p = 0; p < 24; p++) {
            unpack2(acc[p], u, v);
            u = __expf(u - mx); v = __expf(v - mx);
            if ((p & 3) == 0) s0 += u + v;
            else if ((p & 3) == 1) s1 += u + v;
            else if ((p & 3) == 2) s2 += u + v;
            else s3 += u + v;
            acc[p] = pack2(u, v);
        }
        float e48 = __expf(x48 - mx);
        float sum = ((s0 + s1) + (s2 + s3)) + e48;
        acc[24] = pack2(e48, 0.f);
        float inv = 1.0f / sum;
        unsigned long long inv2 = pack2(inv, inv);
        #pragma unroll
        for (int p = 0; p < 25; p++) acc[p] = mul2(acc[p], inv2);
        acc[25] = 0ull;
    }

    // ---- phase 2: score[c][row] = sum_s p[s] * k[c][s] (V := K) ----
    float* __restrict__ og = out_score + (size_t)bh * (DK * LW);
    #pragma unroll 2
    for (int c = 0; c < DK; c++) {
        const uint32_t rowb = ksb + (uint32_t)(c * LP) * 4u;
        unsigned long long s0 = 0ull, s1 = 0ull;
        #pragma unroll
        for (int j = 0; j < 13; j++) {
            unsigned long long k0, k1;
            lds_v2u64(rowb + j * 16, k0, k1);
            s0 = fma2(acc[2 * j], k0, s0);
            s1 = fma2(acc[2 * j + 1], k1, s1);
        }
        float a, bb, x, y;
        unpack2(s0, a, bb);
        unpack2(s1, x, y);
        if (valid) og[c * LW + row] = (a + x) + (bb + y);
    }

    // ---- attn write-out, staging through ks[pairi] (dead after phase 2) ----
    // pair-scoped barrier: both warps of the pair (64 threads)
    #define PBAR() asm volatile("bar.sync %0, 64;" :: "r"(pairi + 1) : "memory")

    float* __restrict__ ag = out_attn + (size_t)bh * (LW * LW);

    // chunk A: rows 0..31 (sub==0 threads own them), 32*50 = 1600 <= 1664 floats
    PBAR();
    if (sub == 0) {
        #pragma unroll
        for (int p = 0; p < 25; p++)
            sts_u64(ksb + (uint32_t)(lane * RST) * 4u + p * 8, acc[p]);
    }
    PBAR();
    for (int i = tid64; i < 32 * LW; i += 64) {
        int t = i / LW, s = i - t * LW;
        ag[i] = ks[pairi][t * RST + s];
    }
    PBAR();

    // chunk B: rows 32..48 (sub==1, lanes 0..16 own them), 17*50 = 850 floats
    if (sub == 1 && valid) {
        #pragma unroll
        for (int p = 0; p < 25; p++)
            sts_u64(ksb + (uint32_t)(lane * RST) * 4u + p * 8, acc[p]);
    }
    PBAR();
    for (int i = tid64; i < 17 * LW; i += 64) {
        int t = i / LW, s = i - t * LW;
        ag[32 * LW + i] = ks[pairi][t * RST + s];
    }
    #undef PBAR
}

extern "C" void kernel_launch(void* const* d_in, const int* in_sizes, int n_in,
                              void* d_out, int out_size) {
    const float* q     = (const float*)d_in[0];
    const float* k     = (const float*)d_in[1];
    // d_in[2] (v) unused: reference sets v := k
    const float* mask  = (const float*)d_in[3];
    const float* table = (const float*)d_in[4];
    const int*   idx   = (const int*)d_in[5];

    float* out       = (float*)d_out;
    float* out_score = out;                            // 2048*256*49
    float* out_attn  = out + (size_t)2048 * 256 * 49;  // 2048*8*49*49

    bm_prep_kernel<<<NH * NW, 256>>>(table, idx, mask);
    win_attn_kernel<<<NW * NH * 16, 128>>>(q, k, out_score, out_attn);
}

// round 16
// speedup vs baseline: 1.3593x; 1.3363x over previous
#include <cuda_runtime.h>
#include <cstdint>

#define LW 49
#define DK 32
#define NH 8
#define NW 64
#define LP 52      // padded k row length (13 float4)
#define RST 50     // bias+mask row stride (8B-aligned pairs)
#define BMSZ 2452  // 49*50 padded to float4 multiple
#define QSZ 1568   // 32*49 flat q tile

// Fused (bias + mask) for each of the 512 (h,w) combos, rows padded to RST.
__device__ float g_bm[NH * NW * BMSZ];

__global__ void bm_prep_kernel(const float* __restrict__ table,
                               const int* __restrict__ idx,
                               const float* __restrict__ mask) {
    const int hw = blockIdx.x;          // h*NW + w
    const int h  = hw >> 6;
    const int w  = hw & (NW - 1);
    float* __restrict__ dst = g_bm + (size_t)hw * BMSZ;
    const float* __restrict__ mg = mask + (size_t)w * (LW * LW);
    for (int i = threadIdx.x; i < BMSZ; i += blockDim.x) {
        int t = i / RST, s = i - t * RST;
        float v = 0.f;
        if (t < LW && s < LW) v = table[idx[t * LW + s] * NH + h] + mg[t * LW + s];
        dst[i] = v;
    }
}

// ---- packed fp32 helpers (Blackwell f32x2 path) ----
__device__ __forceinline__ unsigned long long fma2(unsigned long long a,
                                                   unsigned long long b,
                                                   unsigned long long c) {
    unsigned long long d;
    asm("fma.rn.f32x2 %0, %1, %2, %3;" : "=l"(d) : "l"(a), "l"(b), "l"(c));
    return d;
}
__device__ __forceinline__ unsigned long long mul2(unsigned long long a,
                                                   unsigned long long b) {
    unsigned long long d;
    asm("mul.rn.f32x2 %0, %1, %2;" : "=l"(d) : "l"(a), "l"(b));
    return d;
}
__device__ __forceinline__ unsigned long long pack2(float x, float y) {
    unsigned long long d;
    asm("mov.b64 %0, {%1, %2};" : "=l"(d) : "f"(x), "f"(y));
    return d;
}
__device__ __forceinline__ void unpack2(unsigned long long p, float& x, float& y) {
    asm("mov.b64 {%0, %1}, %2;" : "=f"(x), "=f"(y) : "l"(p));
}
__device__ __forceinline__ void lds_v2u64(uint32_t a, unsigned long long& x,
                                          unsigned long long& y) {
    asm volatile("ld.shared.v2.u64 {%0, %1}, [%2];" : "=l"(x), "=l"(y) : "r"(a));
}
__device__ __forceinline__ unsigned long long lds_u64(uint32_t a) {
    unsigned long long v;
    asm volatile("ld.shared.u64 %0, [%1];" : "=l"(v) : "r"(a));
    return v;
}
__device__ __forceinline__ void sts_u64(uint32_t a, unsigned long long v) {
    asm volatile("st.shared.u64 [%0], %1;" :: "r"(a), "l"(v));
}
__device__ __forceinline__ float lds_f32(uint32_t a) {
    float v;
    asm volatile("ld.shared.f32 %0, [%1];" : "=f"(v) : "r"(a));
    return v;
}

// CTA = 64 threads = 2 warps = 2 (b,h) pairs sharing one (h,w) bias+mask tile.
// Warp = one pair; lane i computes attention rows i and i+32.
__global__ __launch_bounds__(64)
void win_attn_kernel(const float* __restrict__ q,
                     const float* __restrict__ k,
                     float* __restrict__ out_score,
                     float* __restrict__ out_attn) {
    __shared__ __align__(16) float qs[2][QSZ];      // flat [c*49+t]
    __shared__ __align__(16) float ks[2][DK * LP];  // padded [c*52+t]
    __shared__ __align__(16) float bm[BMSZ];

    const int tid  = threadIdx.x;
    const int wid  = tid >> 5;            // pair index within CTA
    const int lane = tid & 31;

    const int cta = blockIdx.x;           // 64*8*16 = 8192 CTAs
    const int w   = cta & 63;
    const int h   = (cta >> 6) & 7;
    const int grp = cta >> 9;             // 0..15
    const int b   = w + 64 * (grp * 2 + wid);
    const int bh  = b * 8 + h;

    const float* __restrict__ qg = q + (size_t)bh * QSZ;
    const float* __restrict__ kg = k + (size_t)bh * QSZ;

    // ---- stage q (flat copy), k (de-interleaved to LP), bias+mask (CTA) ----
    for (int i = lane; i < 96; i += 32) {
        int c = i / 3, r = i - c * 3;
        ks[wid][c * LP + 49 + r] = 0.f;
    }
    for (int j = lane; j < 392; j += 32) {
        ((float4*)qs[wid])[j] = ((const float4*)qg)[j];   // layout matches: flat
        float4 kv = ((const float4*)kg)[j];
        float ka[4] = {kv.x, kv.y, kv.z, kv.w};
        int e = j * 4;
        int c = e / LW;
        int t = e - c * LW;
        #pragma unroll
        for (int u = 0; u < 4; u++) {
            ks[wid][c * LP + t] = ka[u];
            if (++t == LW) { t = 0; ++c; }
        }
    }
    {
        const float* __restrict__ bmg = g_bm + (size_t)(h * NW + w) * BMSZ;
        for (int i = tid; i < BMSZ / 4; i += 64)
            ((float4*)bm)[i] = ((const float4*)bmg)[i];
    }
    __syncthreads();

    const uint32_t qsb = (uint32_t)__cvta_generic_to_shared(&qs[wid][0]);
    const uint32_t ksb = (uint32_t)__cvta_generic_to_shared(&ks[wid][0]);
    const uint32_t bmb = (uint32_t)__cvta_generic_to_shared(&bm[0]);

    const int  r0 = lane;
    const bool v1 = (lane < 17);
    const int  r1 = v1 ? lane + 32 : 48;   // clamped; results discarded when !v1

    // ---- phase 1: packed logits, 2 rows/thread; q from SMEM (low latency) ----
    unsigned long long acc0[26], acc1[26];
    #pragma unroll
    for (int p = 0; p < 26; p++) { acc0[p] = 0ull; acc1[p] = 0ull; }

    #pragma unroll 4
    for (int c = 0; c < DK; c++) {
        const uint32_t rowb = ksb + (uint32_t)(c * LP) * 4u;
        float q0 = lds_f32(qsb + (uint32_t)(c * LW + r0) * 4u);  // conflict-free
        float q1 = lds_f32(qsb + (uint32_t)(c * LW + r1) * 4u);
        unsigned long long q0p = pack2(q0, q0);
        unsigned long long q1p = pack2(q1, q1);
        #pragma unroll
        for (int j = 0; j < 13; j++) {
            unsigned long long k0, k1;
            lds_v2u64(rowb + j * 16, k0, k1);
            acc0[2 * j]     = fma2(q0p, k0, acc0[2 * j]);
            acc0[2 * j + 1] = fma2(q0p, k1, acc0[2 * j + 1]);
            acc1[2 * j]     = fma2(q1p, k0, acc1[2 * j]);
            acc1[2 * j + 1] = fma2(q1p, k1, acc1[2 * j + 1]);
        }
    }

    // ---- softmax (packed; 4-way tree reductions for max and sum) ----
    const float scale = 0.17677669529663687f;  // 32^-0.5
    const unsigned long long scale2 = pack2(scale, scale);
    const uint32_t bmr0 = bmb + (uint32_t)(r0 * RST) * 4u;
    const uint32_t bmr1 = bmb + (uint32_t)(r1 * RST) * 4u;

    #define SOFTMAX_ROW(ACC, BMR)                                            \
    {                                                                        \
        float u, v;                                                          \
        float m0 = -1e30f, m1 = -1e30f, m2 = -1e30f, m3 = -1e30f;            \
        _Pragma("unroll")                                                    \
        for (int p = 0; p < 24; p++) {                                       \
            ACC[p] = fma2(ACC[p], scale2, lds_u64(BMR + p * 8));             \
            unpack2(ACC[p], u, v);                                           \
            float uv = fmaxf(u, v);                                          \
            if ((p & 3) == 0) m0 = fmaxf(m0, uv);                            \
            else if ((p & 3) == 1) m1 = fmaxf(m1, uv);                       \
            else if ((p & 3) == 2) m2 = fmaxf(m2, uv);                       \
            else m3 = fmaxf(m3, uv);                                         \
        }                                                                    \
        unpack2(ACC[24], u, v);                                              \
        float x48 = fmaf(u, scale, lds_f32(BMR + 48 * 4));                   \
        float mx = fmaxf(fmaxf(fmaxf(m0, m1), fmaxf(m2, m3)), x48);          \
        float s0 = 0.f, s1 = 0.f, s2 = 0.f, s3 = 0.f;                        \
        _Pragma("unroll")                                                    \
        for (int p = 0; p < 24; p++) {                                       \
            unpack2(ACC[p], u, v);                                           \
            u = __expf(u - mx); v = __expf(v - mx);                          \
            if ((p & 3) == 0) s0 += u + v;                                   \
            else if ((p & 3) == 1) s1 += u + v;                              \
            else if ((p & 3) == 2) s2 += u + v;                              \
            else s3 += u + v;                                                \
            ACC[p] = pack2(u, v);                                            \
        }                                                                    \
        float e48 = __expf(x48 - mx);                                        \
        float sum = ((s0 + s1) + (s2 + s3)) + e48;                           \
        ACC[24] = pack2(e48, 0.f);                                           \
        float inv = 1.0f / sum;                                              \
        unsigned long long inv2 = pack2(inv, inv);                           \
        _Pragma("unroll")                                                    \
        for (int p = 0; p < 25; p++) ACC[p] = mul2(ACC[p], inv2);            \
        ACC[25] = 0ull;                                                      \
    }

    SOFTMAX_ROW(acc0, bmr0)
    SOFTMAX_ROW(acc1, bmr1)

    // ---- phase 2: score[c][t] = sum_s p[s] * k[c][s] (V := K) ----
    float* __restrict__ og = out_score + (size_t)bh * (DK * LW);
    #pragma unroll 2
    for (int c = 0; c < DK; c++) {
        const uint32_t rowb = ksb + (uint32_t)(c * LP) * 4u;
        unsigned long long s0 = 0ull, s1 = 0ull;
        #pragma unroll
        for (int j = 0; j < 13; j++) {
            unsigned long long k0, k1;
            lds_v2u64(rowb + j * 16, k0, k1);
            s0 = fma2(acc0[2 * j], k0, s0);
            s0 = fma2(acc0[2 * j + 1], k1, s0);
            s1 = fma2(acc1[2 * j], k0, s1);
            s1 = fma2(acc1[2 * j + 1], k1, s1);
        }
        float a, bb, x, y;
        unpack2(s0, a, bb);
        unpack2(s1, x, y);
        og[c * LW + r0] = a + bb;
        if (v1) og[c * LW + r1] = x + y;
    }
    __syncwarp();

    // ---- attn write-out, staging through ks[wid] (dead after phase 2) ----
    float* __restrict__ ag = out_attn + (size_t)bh * (LW * LW);

    // chunk A: rows 0..31 (each lane's r0 row), 32*50 = 1600 <= 1664 floats
    #pragma unroll
    for (int p = 0; p < 25; p++) sts_u64(ksb + (uint32_t)(lane * RST) * 4u + p * 8, acc0[p]);
    __syncwarp();
    for (int i = lane; i < 32 * LW; i += 32) {
        int t = i / LW, s = i - t * LW;
        ag[i] = ks[wid][t * RST + s];
    }
    __syncwarp();

    // chunk B: rows 32..48 (lanes 0..16 hold them), 17*50 = 850 floats
    if (v1) {
        #pragma unroll
        for (int p = 0; p < 25; p++) sts_u64(ksb + (uint32_t)(lane * RST) * 4u + p * 8, acc1[p]);
    }
    __syncwarp();
    for (int i = lane; i < 17 * LW; i += 32) {
        int t = i / LW, s = i - t * LW;
        ag[32 * LW + i] = ks[wid][t * RST + s];
    }
}

extern "C" void kernel_launch(void* const* d_in, const int* in_sizes, int n_in,
                              void* d_out, int out_size) {
    const float* q     = (const float*)d_in[0];
    const float* k     = (const float*)d_in[1];
    // d_in[2] (v) unused: reference sets v := k
    const float* mask  = (const float*)d_in[3];
    const float* table = (const float*)d_in[4];
    const int*   idx   = (const int*)d_in[5];

    float* out       = (float*)d_out;
    float* out_score = out;                            // 2048*256*49
    float* out_attn  = out + (size_t)2048 * 256 * 49;  // 2048*8*49*49

    bm_prep_kernel<<<NH * NW, 256>>>(table, idx, mask);
    win_attn_kernel<<<NW * NH * 16, 64>>>(q, k, out_score, out_attn);
}

// round 17
// speedup vs baseline: 1.4782x; 1.0875x over previous
#include <cuda_runtime.h>
#include <cstdint>

#define LW 49
#define DK 32
#define NH 8
#define NW 64
#define LP 52      // padded k row length (13 float4)
#define RST 50     // bias+mask / staging row stride
#define BMSZ 2452  // 49*50 padded to float4 multiple
#define QSZ 1568   // 32*49 flat q tile
#define LOG2E 1.4426950408889634f

// Fused (bias + mask) * log2e for each of the 512 (h,w) combos, rows padded
// to RST with -1e30 (so exp of pad cols is exactly 0 -> uniform softmax).
__device__ float g_bm[NH * NW * BMSZ];

__global__ void bm_prep_kernel(const float* __restrict__ table,
                               const int* __restrict__ idx,
                               const float* __restrict__ mask) {
    int gi = blockIdx.x * blockDim.x + threadIdx.x;
    if (gi >= NH * NW * BMSZ) return;
    int hw = gi / BMSZ;
    int i  = gi - hw * BMSZ;
    int h  = hw >> 6, w = hw & (NW - 1);
    int t  = i / RST, s = i - t * RST;
    float v = -1e30f;
    if (t < LW && s < LW)
        v = (table[idx[t * LW + s] * NH + h] +
             mask[(size_t)w * LW * LW + t * LW + s]) * LOG2E;
    g_bm[gi] = v;
}

// ---- packed fp32 helpers (Blackwell f32x2 path) ----
__device__ __forceinline__ unsigned long long fma2(unsigned long long a,
                                                   unsigned long long b,
                                                   unsigned long long c) {
    unsigned long long d;
    asm("fma.rn.f32x2 %0, %1, %2, %3;" : "=l"(d) : "l"(a), "l"(b), "l"(c));
    return d;
}
__device__ __forceinline__ unsigned long long mul2(unsigned long long a,
                                                   unsigned long long b) {
    unsigned long long d;
    asm("mul.rn.f32x2 %0, %1, %2;" : "=l"(d) : "l"(a), "l"(b));
    return d;
}
__device__ __forceinline__ unsigned long long pack2(float x, float y) {
    unsigned long long d;
    asm("mov.b64 %0, {%1, %2};" : "=l"(d) : "f"(x), "f"(y));
    return d;
}
__device__ __forceinline__ void unpack2(unsigned long long p, float& x, float& y) {
    asm("mov.b64 {%0, %1}, %2;" : "=f"(x), "=f"(y) : "l"(p));
}
__device__ __forceinline__ void lds_v2u64(uint32_t a, unsigned long long& x,
                                          unsigned long long& y) {
    asm volatile("ld.shared.v2.u64 {%0, %1}, [%2];" : "=l"(x), "=l"(y) : "r"(a));
}
__device__ __forceinline__ unsigned long long lds_u64(uint32_t a) {
    unsigned long long v;
    asm volatile("ld.shared.u64 %0, [%1];" : "=l"(v) : "r"(a));
    return v;
}
__device__ __forceinline__ void sts_u64(uint32_t a, unsigned long long v) {
    asm volatile("st.shared.u64 [%0], %1;" :: "r"(a), "l"(v));
}
__device__ __forceinline__ float lds_f32(uint32_t a) {
    float v;
    asm volatile("ld.shared.f32 %0, [%1];" : "=f"(v) : "r"(a));
    return v;
}
__device__ __forceinline__ float ex2f(float x) {
    float y;
    asm("ex2.approx.f32 %0, %1;" : "=f"(y) : "f"(x));
    return y;
}
__device__ __forceinline__ float rcpf(float x) {
    float y;
    asm("rcp.approx.f32 %0, %1;" : "=f"(y) : "f"(x));
    return y;
}

// CTA = 64 threads = 2 warps = 2 (b,h) pairs sharing one (h,w) bias+mask tile.
// Warp = one pair; lane i computes attention rows i and i+32.
__global__ __launch_bounds__(64)
void win_attn_kernel(const float* __restrict__ q,
                     const float* __restrict__ k,
                     float* __restrict__ out_score,
                     float* __restrict__ out_attn) {
    __shared__ __align__(16) float qs[2][QSZ];      // flat [c*49+t]
    __shared__ __align__(16) float ks[2][DK * LP];  // padded [c*52+t]
    __shared__ __align__(16) float bm[BMSZ];

    const int tid  = threadIdx.x;
    const int wid  = tid >> 5;            // pair index within CTA
    const int lane = tid & 31;

    const int cta = blockIdx.x;           // 64*8*16 = 8192 CTAs
    const int w   = cta & 63;
    const int h   = (cta >> 6) & 7;
    const int grp = cta >> 9;             // 0..15
    const int b   = w + 64 * (grp * 2 + wid);
    const int bh  = b * 8 + h;

    const float* __restrict__ qg = q + (size_t)bh * QSZ;
    const float* __restrict__ kg = k + (size_t)bh * QSZ;

    // ---- stage q (flat copy), k (de-interleaved to LP), bias+mask (CTA) ----
    for (int i = lane; i < 96; i += 32) {
        int c = i / 3, r = i - c * 3;
        ks[wid][c * LP + 49 + r] = 0.f;
    }
    for (int j = lane; j < 392; j += 32) {
        ((float4*)qs[wid])[j] = ((const float4*)qg)[j];   // layout matches: flat
        float4 kv = ((const float4*)kg)[j];
        float ka[4] = {kv.x, kv.y, kv.z, kv.w};
        int e = j * 4;
        int c = e / LW;
        int t = e - c * LW;
        #pragma unroll
        for (int u = 0; u < 4; u++) {
            ks[wid][c * LP + t] = ka[u];
            if (++t == LW) { t = 0; ++c; }
        }
    }
    {
        const float* __restrict__ bmg = g_bm + (size_t)(h * NW + w) * BMSZ;
        for (int i = tid; i < BMSZ / 4; i += 64)
            ((float4*)bm)[i] = ((const float4*)bmg)[i];
    }
    __syncthreads();

    const uint32_t qsb = (uint32_t)__cvta_generic_to_shared(&qs[wid][0]);
    const uint32_t ksb = (uint32_t)__cvta_generic_to_shared(&ks[wid][0]);
    const uint32_t bmb = (uint32_t)__cvta_generic_to_shared(&bm[0]);

    const int  r0 = lane;
    const bool v1 = (lane < 17);
    const int  r1 = v1 ? lane + 32 : 48;   // clamped; results discarded when !v1

    // ---- phase 1: packed logits, 2 rows/thread; q from SMEM ----
    unsigned long long acc0[26], acc1[26];
    #pragma unroll
    for (int p = 0; p < 26; p++) { acc0[p] = 0ull; acc1[p] = 0ull; }

    #pragma unroll 4
    for (int c = 0; c < DK; c++) {
        const uint32_t rowb = ksb + (uint32_t)(c * LP) * 4u;
        float q0 = lds_f32(qsb + (uint32_t)(c * LW + r0) * 4u);  // conflict-free
        float q1 = lds_f32(qsb + (uint32_t)(c * LW + r1) * 4u);
        unsigned long long q0p = pack2(q0, q0);
        unsigned long long q1p = pack2(q1, q1);
        #pragma unroll
        for (int j = 0; j < 13; j++) {
            unsigned long long k0, k1;
            lds_v2u64(rowb + j * 16, k0, k1);
            acc0[2 * j]     = fma2(q0p, k0, acc0[2 * j]);
            acc0[2 * j + 1] = fma2(q0p, k1, acc0[2 * j + 1]);
            acc1[2 * j]     = fma2(q1p, k0, acc1[2 * j]);
            acc1[2 * j + 1] = fma2(q1p, k1, acc1[2 * j + 1]);
        }
    }

    // ---- softmax: single pass, no max-subtraction ----
    // exp(logit*scale + b + m) == ex2(logit*(scale*log2e) + bm_prescaled)
    const float scl = 0.17677669529663687f * LOG2E;  // 32^-0.5 * log2(e)
    const unsigned long long scl2 = pack2(scl, scl);
    const uint32_t bmr0 = bmb + (uint32_t)(r0 * RST) * 4u;
    const uint32_t bmr1 = bmb + (uint32_t)(r1 * RST) * 4u;

    #define SOFTMAX_ROW(ACC, BMR)                                            \
    {                                                                        \
        float u, v;                                                          \
        float s0 = 0.f, s1 = 0.f, s2 = 0.f, s3 = 0.f;                        \
        _Pragma("unroll")                                                    \
        for (int p = 0; p < 25; p++) {                                       \
            ACC[p] = fma2(ACC[p], scl2, lds_u64(BMR + p * 8));               \
            unpack2(ACC[p], u, v);                                           \
            u = ex2f(u); v = ex2f(v);                                        \
            if ((p & 3) == 0) s0 += u + v;                                   \
            else if ((p & 3) == 1) s1 += u + v;                              \
            else if ((p & 3) == 2) s2 += u + v;                              \
            else s3 += u + v;                                                \
            ACC[p] = pack2(u, v);                                            \
        }                                                                    \
        float sum = (s0 + s1) + (s2 + s3);                                   \
        float inv = rcpf(sum);                                               \
        unsigned long long inv2 = pack2(inv, inv);                           \
        _Pragma("unroll")                                                    \
        for (int p = 0; p < 25; p++) ACC[p] = mul2(ACC[p], inv2);            \
        ACC[25] = 0ull;                                                      \
    }

    SOFTMAX_ROW(acc0, bmr0)
    SOFTMAX_ROW(acc1, bmr1)

    // ---- phase 2: score[c][t] = sum_s p[s] * k[c][s] (V := K) ----
    float* __restrict__ og = out_score + (size_t)bh * (DK * LW);
    #pragma unroll 2
    for (int c = 0; c < DK; c++) {
        const uint32_t rowb = ksb + (uint32_t)(c * LP) * 4u;
        unsigned long long s0 = 0ull, s1 = 0ull;
        #pragma unroll
        for (int j = 0; j < 13; j++) {
            unsigned long long k0, k1;
            lds_v2u64(rowb + j * 16, k0, k1);
            s0 = fma2(acc0[2 * j], k0, s0);
            s0 = fma2(acc0[2 * j + 1], k1, s0);
            s1 = fma2(acc1[2 * j], k0, s1);
            s1 = fma2(acc1[2 * j + 1], k1, s1);
        }
        float a, bb, x, y;
        unpack2(s0, a, bb);
        unpack2(s1, x, y);
        og[c * LW + r0] = a + bb;
        if (v1) og[c * LW + r1] = x + y;
    }
    __syncwarp();

    // ---- attn write-out, staging through ks[wid] (dead after phase 2) ----
    float* __restrict__ ag = out_attn + (size_t)bh * (LW * LW);

    // chunk A: rows 0..31 (each lane's r0 row), 32*50 = 1600 <= 1664 floats
    #pragma unroll
    for (int p = 0; p < 25; p++)
        sts_u64(ksb + (uint32_t)(lane * RST) * 4u + p * 8, acc0[p]);
    __syncwarp();
    {
        int s = lane, a = lane;
        for (int i = lane; i < 32 * LW; i += 32) {
            ag[i] = ks[wid][a];
            s += 32; a += 32;
            if (s >= LW) { s -= LW; a += (RST - LW); }
        }
    }
    __syncwarp();

    // chunk B: rows 32..48 (lanes 0..16 hold them), 17*50 = 850 floats
    if (v1) {
        #pragma unroll
        for (int p = 0; p < 25; p++)
            sts_u64(ksb + (uint32_t)(lane * RST) * 4u + p * 8, acc1[p]);
    }
    __syncwarp();
    {
        float* __restrict__ ag2 = ag + 32 * LW;
        int s = lane, a = lane;
        for (int i = lane; i < 17 * LW; i += 32) {
            ag2[i] = ks[wid][a];
            s += 32; a += 32;
            if (s >= LW) { s -= LW; a += (RST - LW); }
        }
    }
}

extern "C" void kernel_launch(void* const* d_in, const int* in_sizes, int n_in,
                              void* d_out, int out_size) {
    const float* q     = (const float*)d_in[0];
    const float* k     = (const float*)d_in[1];
    // d_in[2] (v) unused: reference sets v := k
    const float* mask  = (const float*)d_in[3];
    const float* table = (const float*)d_in[4];
    const int*   idx   = (const int*)d_in[5];

    float* out       = (float*)d_out;
    float* out_score = out;                            // 2048*256*49
    float* out_attn  = out + (size_t)2048 * 256 * 49;  // 2048*8*49*49

    int n_bm = NH * NW * BMSZ;
    bm_prep_kernel<<<(n_bm + 255) / 256, 256>>>(table, idx, mask);
    win_attn_kernel<<<NW * NH * 16, 64>>>(q, k, out_score, out_attn);
}